// round 12
// baseline (speedup 1.0000x reference)
#include <cuda_runtime.h>

#define M_SLOTS 16
#define KEY_DIM 1024
#define TPB     256

// Handshake state. Zero-initialized at load; the last-finishing block of each
// launch resets everything, so every graph replay starts clean (deterministic).
__device__ float        g_dot[M_SLOTS];
__device__ float        g_kk[M_SLOTS];
__device__ float        g_w[M_SLOTS];
__device__ unsigned int g_cnt;    // Phase-A arrival counter
__device__ unsigned int g_flag;   // 1 = weights published
__device__ unsigned int g_done;   // completion counter (reset duty)

// ---------------------------------------------------------------------------
// Phase A for blocks 0..15: block m computes slot m's partials in ONE parallel
// DRAM round-trip (each thread loads one float4 of key + task). The 16th
// arriver computes the softmax and release-publishes g_flag.
// __noinline__ so its registers cannot inflate the streaming path.
// ---------------------------------------------------------------------------
__device__ __noinline__ void phase_a(const float* __restrict__ task_emb,
                                     const float* __restrict__ K_memory,
                                     int m) {
    __shared__ float s_dot[8], s_kk[8], s_tt[8];
    const int tid  = threadIdx.x;
    const int warp = tid >> 5;
    const int lane = tid & 31;

    float4 t = ((const float4*)task_emb)[tid];
    float4 k = ((const float4*)(K_memory + m * KEY_DIM))[tid];

    float dot = t.x * k.x + t.y * k.y + t.z * k.z + t.w * k.w;
    float kk  = k.x * k.x + k.y * k.y + k.z * k.z + k.w * k.w;
    float tt  = t.x * t.x + t.y * t.y + t.z * t.z + t.w * t.w;

    #pragma unroll
    for (int off = 16; off > 0; off >>= 1) {
        dot += __shfl_down_sync(0xffffffffu, dot, off);
        kk  += __shfl_down_sync(0xffffffffu, kk,  off);
        tt  += __shfl_down_sync(0xffffffffu, tt,  off);
    }
    if (lane == 0) { s_dot[warp] = dot; s_kk[warp] = kk; s_tt[warp] = tt; }
    __syncthreads();

    if (tid == 0) {
        float d = 0.f, q = 0.f, r = 0.f;
        #pragma unroll
        for (int w = 0; w < 8; w++) { d += s_dot[w]; q += s_kk[w]; r += s_tt[w]; }
        g_dot[m] = d;
        g_kk[m]  = q;
        __threadfence();                          // publish partials
        unsigned int old = atomicAdd(&g_cnt, 1u);
        if (old == (unsigned)(M_SLOTS - 1)) {     // last arriver finalizes
            __threadfence();                      // see all partials
            float n1 = sqrtf(r);                  // own tt == ||task||^2
            float c[M_SLOTS];
            float mx = -1e30f;
            #pragma unroll
            for (int j = 0; j < M_SLOTS; j++) {
                c[j] = g_dot[j] / fmaxf(n1 * sqrtf(g_kk[j]), 1e-6f);
                mx = fmaxf(mx, c[j]);
            }
            float sum = 0.f;
            #pragma unroll
            for (int j = 0; j < M_SLOTS; j++) { c[j] = __expf(c[j] - mx); sum += c[j]; }
            float inv = 1.0f / sum;
            #pragma unroll
            for (int j = 0; j < M_SLOTS; j++) g_w[j] = c[j] * inv;
            __threadfence();
            unsigned int* fp = &g_flag;
            asm volatile("st.release.gpu.u32 [%0], %1;" :: "l"(fp), "r"(1u) : "memory");
        }
    }
    // no trailing __syncthreads needed: all threads fall through to the
    // common spin gate, which tid0 passes only after the flag is set.
}

// ---------------------------------------------------------------------------
// Single fused kernel. Streaming body identical to the proven 53.8us loop.
// vs R9: Phase A parallel over 16 blocks; BUSY spin (no __nanosleep — its
// coarse wake granularity was the ~5us prologue in R9/R10).
// ---------------------------------------------------------------------------
__global__ void __launch_bounds__(TPB, 8) fused_kernel(
        const float*  __restrict__ task_emb,
        const float*  __restrict__ K_memory,
        const float4* __restrict__ V0,
        const float4* __restrict__ V1,
        float4*       __restrict__ out,
        int nv4_0, int nv4_1) {
    __shared__ float s_w[M_SLOTS];
    const int tid = threadIdx.x;

    if (blockIdx.x < M_SLOTS)
        phase_a(task_emb, K_memory, blockIdx.x);

    // Gate: wait for published weights (busy spin, self-throttled by L2 lat).
    if (tid == 0) {
        unsigned int* fp = &g_flag;
        unsigned int f;
        do {
            asm volatile("ld.acquire.gpu.u32 %0, [%1];" : "=r"(f) : "l"(fp) : "memory");
        } while (!f);
    }
    __syncthreads();                    // tid0's acquire orders the reads below
    if (tid < M_SLOTS) s_w[tid] = g_w[tid];
    __syncthreads();

    // ---------------- streaming weighted sum (proven body) ----------------
    const int i = blockIdx.x * TPB + tid;   // grid is an exact fit
    const float4* __restrict__ V;
    size_t stride;
    int idx;
    if (i < nv4_0) { V = V0; idx = i;          stride = (size_t)nv4_0; }
    else           { V = V1; idx = i - nv4_0;  stride = (size_t)nv4_1; }

    float4 acc = make_float4(0.f, 0.f, 0.f, 0.f);
    #pragma unroll
    for (int m = 0; m < M_SLOTS; m++) {
        float4 v = V[(size_t)m * stride + (size_t)idx];
        float wm = s_w[m];
        acc.x = fmaf(wm, v.x, acc.x);
        acc.y = fmaf(wm, v.y, acc.y);
        acc.z = fmaf(wm, v.z, acc.z);
        acc.w = fmaf(wm, v.w, acc.w);
    }
    out[i] = acc;

    // ---------------- reset handshake for the next graph replay ------------
    if (tid == 0) {
        __threadfence();
        unsigned int d = atomicAdd(&g_done, 1u);
        if (d == gridDim.x - 1) {       // last block: all gates passed
            g_done = 0;
            g_flag = 0;
            g_cnt  = 0;
        }
    }
}

// ---------------------------------------------------------------------------
// Launch contract
// Inputs (metadata order): task_emb [1,1024] f32, K_memory [16,1024] f32,
//                          V0 [16,1024,1024] f32, V1 [16,1024,4096] f32
// Output: rec0 [1024,1024] f32 followed by rec1 [1024,4096] f32
// ---------------------------------------------------------------------------
extern "C" void kernel_launch(void* const* d_in, const int* in_sizes, int n_in,
                              void* d_out, int out_size) {
    const float* task_emb = (const float*)d_in[0];
    const float* K_memory = (const float*)d_in[1];
    const float* V0       = (const float*)d_in[2];
    const float* V1       = (const float*)d_in[3];
    float* out = (float*)d_out;

    const int n0 = in_sizes[2] / M_SLOTS;   // 1024*1024
    const int n1 = in_sizes[3] / M_SLOTS;   // 1024*4096
    const int nv4_0 = n0 / 4;               // 262144
    const int nv4_1 = n1 / 4;               // 1048576
    const int total = nv4_0 + nv4_1;        // 1310720 = 5120 * 256 exactly

    fused_kernel<<<total / TPB, TPB>>>(task_emb, K_memory,
                                       (const float4*)V0, (const float4*)V1,
                                       (float4*)out, nv4_0, nv4_1);
}